// round 3
// baseline (speedup 1.0000x reference)
#include <cuda_runtime.h>
#include <cstdint>

#define BB   2
#define SS   2048
#define HH   16
#define DK   64
#define DM   1024
#define MM   (BB*SS)
#define OUT_ELEMS  (4194304)

// Scratch (allocation-free rule: device globals)
__device__ float g_q [BB*HH*SS*DK];   // [bh][s][d]
__device__ float g_k [BB*HH*SS*DK];   // [bh][s][d]
__device__ float g_v [BB*HH*DK*SS];   // TRANSPOSED: [bh][d][s]  (makes PV an NT GEMM)
__device__ float g_ao[MM*DM];         // attn_out, (b,s,h,d) flat

// ---------------------------------------------------------------------------
// tf32 helpers
// ---------------------------------------------------------------------------
__device__ __forceinline__ uint32_t f2tf(float x) {
    uint32_t u; asm("cvt.rna.tf32.f32 %0, %1;" : "=r"(u) : "f"(x)); return u;
}

__device__ __forceinline__ void mma8(float* c, const uint32_t* a, const uint32_t* b) {
    asm volatile("mma.sync.aligned.m16n8k8.row.col.f32.tf32.tf32.f32 "
        "{%0,%1,%2,%3},{%4,%5,%6,%7},{%8,%9},{%0,%1,%2,%3};"
        : "+f"(c[0]), "+f"(c[1]), "+f"(c[2]), "+f"(c[3])
        : "r"(a[0]), "r"(a[1]), "r"(a[2]), "r"(a[3]), "r"(b[0]), "r"(b[1]));
}

// ---------------------------------------------------------------------------
// Tensor-core NT GEMM: C = scale*(A @ B^T) (+bias). A:[M,K], B:[N,K] row-major.
// SPLIT: 1 = plain tf32, 2 = split A (2 mma), 3 = split A and B (3 mma, ~fp32)
// MODE:  0 = row-major C (batched via sC)
//        1 = scatter to head-major [b,h,s,d]   (q/k projections)
//        2 = scatter to head-major [b,h,d,s]   (v projection, transposed)
//        3 = scatter to (b,s,h,d) flat, b/h from blockIdx.z   (PV output)
// ---------------------------------------------------------------------------
template<int BM, int BN, int BK, int WM, int WN, int SPLIT, int MODE>
__global__ void __launch_bounds__(256, 1) gemm_tc(
    const float* __restrict__ A, const float* __restrict__ B,
    const float* __restrict__ bias, float* __restrict__ C,
    int M, int N, int K, long long sA, long long sB, long long sC, float scale)
{
    constexpr int SK = BK + 4;                 // padded smem stride (floats)
    constexpr int MW = BM / WM;
    constexpr int MF = WM / 16, NF = WN / 8, KS = BK / 8;
    constexpr int AV = (BM * BK) / (4 * 256);  // float4 loads per thread (A)
    constexpr int BV = (BN * BK) / (4 * 256);
    constexpr int KC = BK / 4;                 // float4 columns per row
    static_assert(AV >= 1 && BV >= 1, "tile too small");

    __shared__ float Ah[BM * SK];
    __shared__ float Bh[BN * SK];
    __shared__ float Al[(SPLIT >= 2) ? BM * SK : 1];
    __shared__ float Bl[(SPLIT >= 3) ? BN * SK : 1];

    A += (long long)blockIdx.z * sA;
    B += (long long)blockIdx.z * sB;

    const int tid = threadIdx.x;
    const int w = tid >> 5, lane = tid & 31;
    const int g = lane >> 2, t = lane & 3;
    const int m0 = blockIdx.y * BM, n0 = blockIdx.x * BN;
    const int wm0 = (w % MW) * WM, wn0 = (w / MW) * WN;

    float acc[MF][NF][4];
    #pragma unroll
    for (int i = 0; i < MF; i++)
        #pragma unroll
        for (int j = 0; j < NF; j++)
            #pragma unroll
            for (int e = 0; e < 4; e++) acc[i][j][e] = 0.f;

    float4 ra[AV], rb[BV];

    // prologue: load chunk k0=0
    #pragma unroll
    for (int i = 0; i < AV; i++) {
        int idx = tid + i * 256;
        ra[i] = *(const float4*)(A + (long long)(m0 + idx / KC) * K + (idx % KC) * 4);
    }
    #pragma unroll
    for (int i = 0; i < BV; i++) {
        int idx = tid + i * 256;
        rb[i] = *(const float4*)(B + (long long)(n0 + idx / KC) * K + (idx % KC) * 4);
    }

    for (int k0 = 0; k0 < K; k0 += BK) {
        __syncthreads();
        // stage to smem, converting to tf32 hi/lo once
        #pragma unroll
        for (int i = 0; i < AV; i++) {
            int idx = tid + i * 256, r = idx / KC, c = (idx % KC) * 4;
            float v[4] = {ra[i].x, ra[i].y, ra[i].z, ra[i].w};
            #pragma unroll
            for (int j = 0; j < 4; j++) {
                uint32_t hb = f2tf(v[j]);
                Ah[r * SK + c + j] = __uint_as_float(hb);
                if (SPLIT >= 2)
                    Al[r * SK + c + j] = __uint_as_float(f2tf(v[j] - __uint_as_float(hb)));
            }
        }
        #pragma unroll
        for (int i = 0; i < BV; i++) {
            int idx = tid + i * 256, r = idx / KC, c = (idx % KC) * 4;
            float v[4] = {rb[i].x, rb[i].y, rb[i].z, rb[i].w};
            #pragma unroll
            for (int j = 0; j < 4; j++) {
                uint32_t hb = f2tf(v[j]);
                Bh[r * SK + c + j] = __uint_as_float(hb);
                if (SPLIT >= 3)
                    Bl[r * SK + c + j] = __uint_as_float(f2tf(v[j] - __uint_as_float(hb)));
            }
        }
        __syncthreads();

        // prefetch next chunk into registers (overlaps with compute)
        if (k0 + BK < K) {
            #pragma unroll
            for (int i = 0; i < AV; i++) {
                int idx = tid + i * 256;
                ra[i] = *(const float4*)(A + (long long)(m0 + idx / KC) * K + k0 + BK + (idx % KC) * 4);
            }
            #pragma unroll
            for (int i = 0; i < BV; i++) {
                int idx = tid + i * 256;
                rb[i] = *(const float4*)(B + (long long)(n0 + idx / KC) * K + k0 + BK + (idx % KC) * 4);
            }
        }

        #pragma unroll
        for (int ks = 0; ks < KS; ks++) {
            uint32_t af [MF][4];
            uint32_t afl[(SPLIT >= 2) ? MF : 1][4];
            uint32_t bf [NF][2];
            uint32_t bfl[(SPLIT >= 3) ? NF : 1][2];

            #pragma unroll
            for (int mf = 0; mf < MF; mf++) {
                int r0 = (wm0 + mf * 16 + g) * SK + ks * 8 + t;
                int r1 = r0 + 8 * SK;
                af[mf][0] = __float_as_uint(Ah[r0]);
                af[mf][1] = __float_as_uint(Ah[r1]);
                af[mf][2] = __float_as_uint(Ah[r0 + 4]);
                af[mf][3] = __float_as_uint(Ah[r1 + 4]);
                if (SPLIT >= 2) {
                    afl[mf][0] = __float_as_uint(Al[r0]);
                    afl[mf][1] = __float_as_uint(Al[r1]);
                    afl[mf][2] = __float_as_uint(Al[r0 + 4]);
                    afl[mf][3] = __float_as_uint(Al[r1 + 4]);
                }
            }
            #pragma unroll
            for (int nf = 0; nf < NF; nf++) {
                int c0 = (wn0 + nf * 8 + g) * SK + ks * 8 + t;
                bf[nf][0] = __float_as_uint(Bh[c0]);
                bf[nf][1] = __float_as_uint(Bh[c0 + 4]);
                if (SPLIT >= 3) {
                    bfl[nf][0] = __float_as_uint(Bl[c0]);
                    bfl[nf][1] = __float_as_uint(Bl[c0 + 4]);
                }
            }

            #pragma unroll
            for (int mf = 0; mf < MF; mf++)
                #pragma unroll
                for (int nf = 0; nf < NF; nf++) {
                    if (SPLIT >= 2) mma8(acc[mf][nf], afl[mf], bf[nf]);
                    if (SPLIT >= 3) mma8(acc[mf][nf], af[mf], bfl[nf]);
                    mma8(acc[mf][nf], af[mf], bf[nf]);
                }
        }
    }

    // epilogue
    const int bz = blockIdx.z;
    #pragma unroll
    for (int mf = 0; mf < MF; mf++) {
        #pragma unroll
        for (int nf = 0; nf < NF; nf++) {
            #pragma unroll
            for (int e = 0; e < 4; e++) {
                int m = m0 + wm0 + mf * 16 + g + ((e >= 2) ? 8 : 0);
                int n = n0 + wn0 + nf * 8 + 2 * t + (e & 1);
                float v = acc[mf][nf][e] * scale;
                if (bias) v += bias[n];
                if (MODE == 0) {
                    C[(long long)bz * sC + (long long)m * N + n] = v;
                } else if (MODE == 1) {
                    C[(((long long)((m >> 11) * HH + (n >> 6))) * SS + (m & (SS - 1))) * DK + (n & (DK - 1))] = v;
                } else if (MODE == 2) {
                    C[(((long long)((m >> 11) * HH + (n >> 6))) * DK + (n & (DK - 1))) * SS + (m & (SS - 1))] = v;
                } else { // MODE 3
                    int b = bz >> 4, h = bz & 15;
                    C[((long long)(b * SS + m)) * DM + h * DK + n] = v;
                }
            }
        }
    }
}

// ---------------------------------------------------------------------------
// Sparsemax (in-place per row of 2048). One block (256 thr) per row.
// ---------------------------------------------------------------------------
template<int OP> // 0=sum, 1=max
__device__ __forceinline__ float blockReduce(float v, float* sh)
{
    const int tid = threadIdx.x, l = tid & 31, w = tid >> 5;
    #pragma unroll
    for (int o = 16; o; o >>= 1) {
        float u = __shfl_xor_sync(0xffffffffu, v, o);
        v = OP ? fmaxf(v, u) : v + u;
    }
    if (l == 0) sh[w] = v;
    __syncthreads();
    if (tid < 32) {
        v = (l < 8) ? sh[l] : (OP ? -1e30f : 0.f);
        #pragma unroll
        for (int o = 4; o; o >>= 1) {
            float u = __shfl_xor_sync(0xffffffffu, v, o);
            v = OP ? fmaxf(v, u) : v + u;
        }
        if (l == 0) sh[0] = v;
    }
    __syncthreads();
    float r = sh[0];
    __syncthreads();
    return r;
}

__global__ void __launch_bounds__(256) sparsemax_kernel(float* __restrict__ attn)
{
    __shared__ float sh[32];
    float* z = attn + (long long)blockIdx.x * SS;
    const int tid = threadIdx.x;

    float v[8];
    #pragma unroll
    for (int i = 0; i < 8; i++) v[i] = z[tid + i * 256];

    float mx = -1e30f;
    #pragma unroll
    for (int i = 0; i < 8; i++) mx = fmaxf(mx, v[i]);
    mx = blockReduce<1>(mx, sh);

    // Bisection on f(tau) = sum(max(z - tau, 0)); tau* in [mx-1, mx]
    float lo = mx - 1.f, hi = mx;
    for (int it = 0; it < 20; it++) {
        float mid = 0.5f * (lo + hi);
        float s = 0.f;
        #pragma unroll
        for (int i = 0; i < 8; i++) s += fmaxf(v[i] - mid, 0.f);
        s = blockReduce<0>(s, sh);
        if (s >= 1.f) lo = mid; else hi = mid;
    }

    // Michelot refinement from a lower bound: converges to exact tau*
    float tau = lo;
    for (int it = 0; it < 6; it++) {
        float s = 0.f, c = 0.f;
        #pragma unroll
        for (int i = 0; i < 8; i++)
            if (v[i] > tau) { s += v[i]; c += 1.f; }
        s = blockReduce<0>(s, sh);
        c = blockReduce<0>(c, sh);
        tau = (s - 1.f) / c;
    }

    #pragma unroll
    for (int i = 0; i < 8; i++) z[tid + i * 256] = fmaxf(v[i] - tau, 0.f);
}

// ---------------------------------------------------------------------------
extern "C" void kernel_launch(void* const* d_in, const int* in_sizes, int n_in,
                              void* d_out, int out_size)
{
    const float* query = (const float*)d_in[0];
    const float* key   = (const float*)d_in[1];
    const float* value = (const float*)d_in[2];
    const float* Wq  = (const float*)d_in[3];  const float* bq  = (const float*)d_in[4];
    const float* Wk  = (const float*)d_in[5];  const float* bk  = (const float*)d_in[6];
    const float* Wv  = (const float*)d_in[7];  const float* bv  = (const float*)d_in[8];
    const float* Wfc = (const float*)d_in[9];  const float* bfc = (const float*)d_in[10];

    float* out  = (float*)d_out;
    float* attn = out + OUT_ELEMS;

    float *pq, *pk, *pv, *pao;
    cudaGetSymbolAddress((void**)&pq,  g_q);
    cudaGetSymbolAddress((void**)&pk,  g_k);
    cudaGetSymbolAddress((void**)&pv,  g_v);
    cudaGetSymbolAddress((void**)&pao, g_ao);

    dim3 blk(256);

    // 1) Projections (3xTF32, ~fp32 accuracy) -> head-major scratch
    gemm_tc<128,128,16,64,32,3,1><<<dim3(DM/128, MM/128, 1), blk>>>(
        query, Wq, bq, pq, MM, DM, DM, 0, 0, 0, 1.f);
    gemm_tc<128,128,16,64,32,3,1><<<dim3(DM/128, MM/128, 1), blk>>>(
        key,   Wk, bk, pk, MM, DM, DM, 0, 0, 0, 1.f);
    gemm_tc<128,128,16,64,32,3,2><<<dim3(DM/128, MM/128, 1), blk>>>(
        value, Wv, bv, pv, MM, DM, DM, 0, 0, 0, 1.f);

    // 2) logits = q @ k^T / 8 (3xTF32) -> attention slice of d_out
    gemm_tc<128,128,16,64,32,3,0><<<dim3(SS/128, SS/128, BB*HH), blk>>>(
        pq, pk, nullptr, attn, SS, SS, DK,
        (long long)SS*DK, (long long)SS*DK, (long long)SS*SS, 0.125f);

    // 3) sparsemax in place
    sparsemax_kernel<<<BB*HH*SS, 256>>>(attn);

    // 4) attn_out = P @ V^T (V stored transposed; split P only) -> (b,s,h,d)
    gemm_tc<128,64,16,32,32,2,3><<<dim3(1, SS/128, BB*HH), blk>>>(
        attn, pv, nullptr, pao, SS, DK, SS,
        (long long)SS*SS, (long long)DK*SS, 0, 1.f);

    // 5) output = attn_out @ Wfc^T + bfc (3xTF32)
    gemm_tc<128,128,16,64,32,3,0><<<dim3(DM/128, MM/128, 1), blk>>>(
        pao, Wfc, bfc, out, MM, DM, DM, 0, 0, 0, 1.f);
}

// round 5
// speedup vs baseline: 2.2915x; 2.2915x over previous
#include <cuda_runtime.h>
#include <cuda_bf16.h>
#include <cstdint>

#define BB   2
#define SS   2048
#define HH   16
#define DK   64
#define DM   1024
#define MM   (BB*SS)
#define OUT_ELEMS  (4194304)

// Scratch (allocation-free rule: device globals)
__device__ float g_q [BB*HH*SS*DK];   // [bh][s][d]
__device__ float g_k [BB*HH*SS*DK];   // [bh][s][d]
__device__ float g_v [BB*HH*DK*SS];   // TRANSPOSED: [bh][d][s]
__device__ float g_ao[MM*DM];         // attn_out, (b,s,h,d) flat

// ---------------------------------------------------------------------------
__device__ __forceinline__ void mma16(float* c, const uint32_t* a, const uint32_t* b) {
    asm volatile("mma.sync.aligned.m16n8k16.row.col.f32.bf16.bf16.f32 "
        "{%0,%1,%2,%3},{%4,%5,%6,%7},{%8,%9},{%0,%1,%2,%3};"
        : "+f"(c[0]), "+f"(c[1]), "+f"(c[2]), "+f"(c[3])
        : "r"(a[0]), "r"(a[1]), "r"(a[2]), "r"(a[3]), "r"(b[0]), "r"(b[1]));
}

__device__ __forceinline__ void ldsm4(uint32_t* r, uint32_t addr) {
    asm volatile("ldmatrix.sync.aligned.m8n8.x4.shared.b16 {%0,%1,%2,%3}, [%4];"
        : "=r"(r[0]), "=r"(r[1]), "=r"(r[2]), "=r"(r[3]) : "r"(addr));
}

// convert 4 floats -> 4 hi-bf16 (8B) + 4 lo-bf16 (8B)
__device__ __forceinline__ void cvt_hilo(const float4 v, uint2* ph, uint2* pl) {
    __nv_bfloat162 h0 = __floats2bfloat162_rn(v.x, v.y);
    __nv_bfloat162 h1 = __floats2bfloat162_rn(v.z, v.w);
    __nv_bfloat162 l0 = __floats2bfloat162_rn(v.x - __bfloat162float(h0.x),
                                              v.y - __bfloat162float(h0.y));
    __nv_bfloat162 l1 = __floats2bfloat162_rn(v.z - __bfloat162float(h1.x),
                                              v.w - __bfloat162float(h1.y));
    *ph = make_uint2(*(uint32_t*)&h0, *(uint32_t*)&h1);
    *pl = make_uint2(*(uint32_t*)&l0, *(uint32_t*)&l1);
}

// ---------------------------------------------------------------------------
// bf16x3 NT GEMM: C = scale*(A @ B^T)(+bias). A:[M,K], B:[N,K] row-major fp32.
// BM=128, BN=64, BK=16. 8 warps (4 along M x 2 along N), warp tile 32x32.
// MODE: 0 = row-major C (batched via sC)
//       1 = scatter head-major [b,h,s,d]   (q/k proj)
//       2 = scatter head-major [b,h,d,s]   (v proj, transposed)
//       3 = scatter (b,s,h,d) flat, b/h from blockIdx.z (PV output)
// ---------------------------------------------------------------------------
template<int MODE>
__global__ void __launch_bounds__(256, 2) gemm_bf(
    const float* __restrict__ A, const float* __restrict__ B,
    const float* __restrict__ bias, float* __restrict__ C,
    int N, int K, long long sA, long long sB, long long sC, float scale)
{
    constexpr int BM = 128, BN = 64, BK = 16;
    constexpr int SK = 24;  // padded row stride in halves (48B: 3r mod 8 -> conflict-free LDSM)

    __shared__ __nv_bfloat16 Ah[BM * SK], Al[BM * SK];
    __shared__ __nv_bfloat16 Bh[BN * SK], Bl[BN * SK];

    A += (long long)blockIdx.z * sA;
    B += (long long)blockIdx.z * sB;

    const int tid = threadIdx.x;
    const int w = tid >> 5, lane = tid & 31;
    const int m0 = blockIdx.y * BM, n0 = blockIdx.x * BN;
    const int wm0 = (w & 3) * 32, wn0 = (w >> 2) * 32;

    // ldmatrix per-lane source offsets (bytes)
    uint32_t a_base  = (uint32_t)__cvta_generic_to_shared(Ah);
    uint32_t al_base = (uint32_t)__cvta_generic_to_shared(Al);
    uint32_t b_base  = (uint32_t)__cvta_generic_to_shared(Bh);
    uint32_t bl_base = (uint32_t)__cvta_generic_to_shared(Bl);
    uint32_t aoff[2], boff[2];
    {
        int rl = lane & 7;
        int arow0 = wm0 + rl + ((lane >> 3) & 1) * 8;
        int acol  = (lane >> 4) * 8;
        aoff[0] = (uint32_t)(((arow0) * SK + acol) * 2);
        aoff[1] = (uint32_t)(((arow0 + 16) * SK + acol) * 2);
        int brow0 = wn0 + rl + (lane >> 4) * 8;
        int bcol  = ((lane >> 3) & 1) * 8;
        boff[0] = (uint32_t)(((brow0) * SK + bcol) * 2);
        boff[1] = (uint32_t)(((brow0 + 16) * SK + bcol) * 2);
    }

    float acc[2][4][4];
    #pragma unroll
    for (int i = 0; i < 2; i++)
        #pragma unroll
        for (int j = 0; j < 4; j++)
            #pragma unroll
            for (int e = 0; e < 4; e++) acc[i][j][e] = 0.f;

    // global-load indices: A: 2 float4/thread, B: 1 float4/thread
    const int ar = tid >> 2, ac = (tid & 3) * 4;    // A rows ar, ar+64
    const int br = tid >> 2, bc = (tid & 3) * 4;    // B row br (0..63)

    float4 ra0, ra1, rb0;
    ra0 = *(const float4*)(A + (long long)(m0 + ar) * K + ac);
    ra1 = *(const float4*)(A + (long long)(m0 + ar + 64) * K + ac);
    rb0 = *(const float4*)(B + (long long)(n0 + br) * K + bc);

    for (int k0 = 0; k0 < K; k0 += BK) {
        __syncthreads();
        cvt_hilo(ra0, (uint2*)&Ah[ar * SK + ac],        (uint2*)&Al[ar * SK + ac]);
        cvt_hilo(ra1, (uint2*)&Ah[(ar + 64) * SK + ac], (uint2*)&Al[(ar + 64) * SK + ac]);
        cvt_hilo(rb0, (uint2*)&Bh[br * SK + bc],        (uint2*)&Bl[br * SK + bc]);
        __syncthreads();

        if (k0 + BK < K) {
            ra0 = *(const float4*)(A + (long long)(m0 + ar) * K + k0 + BK + ac);
            ra1 = *(const float4*)(A + (long long)(m0 + ar + 64) * K + k0 + BK + ac);
            rb0 = *(const float4*)(B + (long long)(n0 + br) * K + k0 + BK + bc);
        }

        uint32_t ah[2][4], al[2][4], bh[2][4], bl[2][4];
        #pragma unroll
        for (int mf = 0; mf < 2; mf++) {
            ldsm4(ah[mf], a_base  + aoff[mf]);
            ldsm4(al[mf], al_base + aoff[mf]);
        }
        #pragma unroll
        for (int p = 0; p < 2; p++) {
            ldsm4(bh[p], b_base  + boff[p]);
            ldsm4(bl[p], bl_base + boff[p]);
        }

        #pragma unroll
        for (int mf = 0; mf < 2; mf++)
            #pragma unroll
            for (int nf = 0; nf < 4; nf++) {
                const uint32_t* bhp = &bh[nf >> 1][(nf & 1) * 2];
                const uint32_t* blp = &bl[nf >> 1][(nf & 1) * 2];
                mma16(acc[mf][nf], al[mf], bhp);
                mma16(acc[mf][nf], ah[mf], blp);
                mma16(acc[mf][nf], ah[mf], bhp);
            }
    }

    // epilogue
    const int bz = blockIdx.z;
    const int g = lane >> 2, t = lane & 3;
    #pragma unroll
    for (int mf = 0; mf < 2; mf++) {
        #pragma unroll
        for (int nf = 0; nf < 4; nf++) {
            #pragma unroll
            for (int e = 0; e < 4; e++) {
                int m = m0 + wm0 + mf * 16 + g + ((e >= 2) ? 8 : 0);
                int n = n0 + wn0 + nf * 8 + 2 * t + (e & 1);
                float v = acc[mf][nf][e] * scale;
                if (bias) v += bias[n];
                if (MODE == 0) {
                    C[(long long)bz * sC + (long long)m * N + n] = v;
                } else if (MODE == 1) {
                    C[(((long long)((m >> 11) * HH + (n >> 6))) * SS + (m & (SS - 1))) * DK + (n & (DK - 1))] = v;
                } else if (MODE == 2) {
                    C[(((long long)((m >> 11) * HH + (n >> 6))) * DK + (n & (DK - 1))) * SS + (m & (SS - 1))] = v;
                } else {
                    int b = bz >> 4, h = bz & 15;
                    C[((long long)(b * SS + m)) * DM + h * DK + n] = v;
                }
            }
        }
    }
}

// ---------------------------------------------------------------------------
// Sparsemax (in-place per row of 2048). One block (256 thr) per row.
// ---------------------------------------------------------------------------
template<int OP> // 0=sum, 1=max
__device__ __forceinline__ float blockReduce(float v, float* sh)
{
    const int tid = threadIdx.x, l = tid & 31, w = tid >> 5;
    #pragma unroll
    for (int o = 16; o; o >>= 1) {
        float u = __shfl_xor_sync(0xffffffffu, v, o);
        v = OP ? fmaxf(v, u) : v + u;
    }
    if (l == 0) sh[w] = v;
    __syncthreads();
    if (tid < 32) {
        v = (l < 8) ? sh[l] : (OP ? -1e30f : 0.f);
        #pragma unroll
        for (int o = 4; o; o >>= 1) {
            float u = __shfl_xor_sync(0xffffffffu, v, o);
            v = OP ? fmaxf(v, u) : v + u;
        }
        if (l == 0) sh[0] = v;
    }
    __syncthreads();
    float r = sh[0];
    __syncthreads();
    return r;
}

__global__ void __launch_bounds__(256) sparsemax_kernel(float* __restrict__ attn)
{
    __shared__ float sh[32];
    float* z = attn + (long long)blockIdx.x * SS;
    const int tid = threadIdx.x;

    float v[8];
    #pragma unroll
    for (int i = 0; i < 8; i++) v[i] = z[tid + i * 256];

    float mx = -1e30f;
    #pragma unroll
    for (int i = 0; i < 8; i++) mx = fmaxf(mx, v[i]);
    mx = blockReduce<1>(mx, sh);

    float lo = mx - 1.f, hi = mx;
    for (int it = 0; it < 20; it++) {
        float mid = 0.5f * (lo + hi);
        float s = 0.f;
        #pragma unroll
        for (int i = 0; i < 8; i++) s += fmaxf(v[i] - mid, 0.f);
        s = blockReduce<0>(s, sh);
        if (s >= 1.f) lo = mid; else hi = mid;
    }

    float tau = lo;
    for (int it = 0; it < 6; it++) {
        float s = 0.f, c = 0.f;
        #pragma unroll
        for (int i = 0; i < 8; i++)
            if (v[i] > tau) { s += v[i]; c += 1.f; }
        s = blockReduce<0>(s, sh);
        c = blockReduce<0>(c, sh);
        tau = (s - 1.f) / c;
    }

    #pragma unroll
    for (int i = 0; i < 8; i++) z[tid + i * 256] = fmaxf(v[i] - tau, 0.f);
}

// ---------------------------------------------------------------------------
extern "C" void kernel_launch(void* const* d_in, const int* in_sizes, int n_in,
                              void* d_out, int out_size)
{
    const float* query = (const float*)d_in[0];
    const float* key   = (const float*)d_in[1];
    const float* value = (const float*)d_in[2];
    const float* Wq  = (const float*)d_in[3];  const float* bq  = (const float*)d_in[4];
    const float* Wk  = (const float*)d_in[5];  const float* bk  = (const float*)d_in[6];
    const float* Wv  = (const float*)d_in[7];  const float* bv  = (const float*)d_in[8];
    const float* Wfc = (const float*)d_in[9];  const float* bfc = (const float*)d_in[10];

    float* out  = (float*)d_out;
    float* attn = out + OUT_ELEMS;

    float *pq, *pk, *pv, *pao;
    cudaGetSymbolAddress((void**)&pq,  g_q);
    cudaGetSymbolAddress((void**)&pk,  g_k);
    cudaGetSymbolAddress((void**)&pv,  g_v);
    cudaGetSymbolAddress((void**)&pao, g_ao);

    dim3 blk(256);

    // 1) Projections -> head-major scratch (v transposed)
    gemm_bf<1><<<dim3(DM/64, MM/128, 1), blk>>>(query, Wq, bq, pq, DM, DM, 0, 0, 0, 1.f);
    gemm_bf<1><<<dim3(DM/64, MM/128, 1), blk>>>(key,   Wk, bk, pk, DM, DM, 0, 0, 0, 1.f);
    gemm_bf<2><<<dim3(DM/64, MM/128, 1), blk>>>(value, Wv, bv, pv, DM, DM, 0, 0, 0, 1.f);

    // 2) logits = q @ k^T / 8 -> attention slice of d_out
    gemm_bf<0><<<dim3(SS/64, SS/128, BB*HH), blk>>>(
        pq, pk, nullptr, attn, SS, DK,
        (long long)SS*DK, (long long)SS*DK, (long long)SS*SS, 0.125f);

    // 3) sparsemax in place
    sparsemax_kernel<<<BB*HH*SS, 256>>>(attn);

    // 4) attn_out = P @ V^T (V stored [d][s]) -> (b,s,h,d)
    gemm_bf<3><<<dim3(DK/64, SS/128, BB*HH), blk>>>(
        attn, pv, nullptr, pao, DK, SS,
        (long long)SS*SS, (long long)DK*SS, 0, 1.f);

    // 5) output = attn_out @ Wfc^T + bfc
    gemm_bf<0><<<dim3(DM/64, MM/128, 1), blk>>>(pao, Wfc, bfc, out, DM, DM, 0, 0, 0, 1.f);
}

// round 7
// speedup vs baseline: 4.2639x; 1.8608x over previous
#include <cuda_runtime.h>
#include <cuda_bf16.h>
#include <cstdint>

#define BB   2
#define SS   2048
#define HH   16
#define DK   64
#define DM   1024
#define MM   (BB*SS)
#define OUT_ELEMS  (4194304)

// Scratch (allocation-free rule: device globals)
__device__ __nv_bfloat16 g_qh[BB*HH*SS*DK];   // q hi, [bh][s][d]
__device__ __nv_bfloat16 g_ql[BB*HH*SS*DK];   // q lo
__device__ __nv_bfloat16 g_kh[BB*HH*SS*DK];   // k hi
__device__ __nv_bfloat16 g_kl[BB*HH*SS*DK];   // k lo
__device__ float g_v [BB*HH*DK*SS];           // v TRANSPOSED: [bh][d][s]
__device__ float g_ao[MM*DM];                 // attn_out, (b,s,h,d) flat

// ---------------------------------------------------------------------------
__device__ __forceinline__ void mma16(float* c, const uint32_t* a, const uint32_t* b) {
    asm volatile("mma.sync.aligned.m16n8k16.row.col.f32.bf16.bf16.f32 "
        "{%0,%1,%2,%3},{%4,%5,%6,%7},{%8,%9},{%0,%1,%2,%3};"
        : "+f"(c[0]), "+f"(c[1]), "+f"(c[2]), "+f"(c[3])
        : "r"(a[0]), "r"(a[1]), "r"(a[2]), "r"(a[3]), "r"(b[0]), "r"(b[1]));
}

__device__ __forceinline__ void ldsm4(uint32_t* r, uint32_t addr) {
    asm volatile("ldmatrix.sync.aligned.m8n8.x4.shared.b16 {%0,%1,%2,%3}, [%4];"
        : "=r"(r[0]), "=r"(r[1]), "=r"(r[2]), "=r"(r[3]) : "r"(addr));
}

__device__ __forceinline__ uint32_t smem_u32(const void* p) {
    return (uint32_t)__cvta_generic_to_shared(p);
}

__device__ __forceinline__ void cp16(uint32_t dst, const void* src) {
    asm volatile("cp.async.cg.shared.global [%0], [%1], 16;" :: "r"(dst), "l"(src));
}

// convert 4 floats -> 4 hi bf16 (8B) + 4 lo bf16 (8B)
__device__ __forceinline__ void cvt_hilo(const float4 v, uint2* ph, uint2* pl) {
    __nv_bfloat162 h0 = __floats2bfloat162_rn(v.x, v.y);
    __nv_bfloat162 h1 = __floats2bfloat162_rn(v.z, v.w);
    __nv_bfloat162 l0 = __floats2bfloat162_rn(v.x - __bfloat162float(h0.x),
                                              v.y - __bfloat162float(h0.y));
    __nv_bfloat162 l1 = __floats2bfloat162_rn(v.z - __bfloat162float(h1.x),
                                              v.w - __bfloat162float(h1.y));
    *ph = make_uint2(*(uint32_t*)&h0, *(uint32_t*)&h1);
    *pl = make_uint2(*(uint32_t*)&l0, *(uint32_t*)&l1);
}

// ===========================================================================
// fp32-input bf16x3 NT GEMM. C = scale*(A @ B^T)(+bias). A:[M,K], B:[N,K].
// BM=128, BN=64, BK=32. 8 warps (4x2), warp tile 32x32.
// MODE: 0 row-major fp32 C (batched via sC)
//       1 bf16 hi/lo pair scatter to head-major [b,h,s,d]  (q/k proj)
//       2 fp32 scatter to head-major [b,h,d,s]             (v proj)
//       3 fp32 scatter to (b,s,h,d), b/h from blockIdx.z   (PV out)
// ===========================================================================
template<int MODE>
__global__ void __launch_bounds__(256, 2) gemm_f32(
    const float* __restrict__ A, const float* __restrict__ B,
    const float* __restrict__ bias, float* __restrict__ C,
    __nv_bfloat16* __restrict__ Ch, __nv_bfloat16* __restrict__ Cl,
    int N, int K, long long sA, long long sB, long long sC, float scale)
{
    constexpr int BK = 32, SK = 40;  // 80B rows: 5r mod 8 -> conflict-free ldsm

    __shared__ __nv_bfloat16 Ah[128 * SK], Al[128 * SK];
    __shared__ __nv_bfloat16 Bh[64 * SK],  Bl[64 * SK];

    const int bz = blockIdx.z;
    A += (long long)bz * sA;
    B += (long long)bz * sB;

    const int tid = threadIdx.x, w = tid >> 5, lane = tid & 31;
    const int g = lane >> 2, t = lane & 3;
    const int m0 = blockIdx.y * 128, n0 = blockIdx.x * 64;
    const int wm0 = (w & 3) * 32, wn0 = (w >> 2) * 32;

    const uint32_t ah_b = smem_u32(Ah), al_b = smem_u32(Al);
    const uint32_t bh_b = smem_u32(Bh), bl_b = smem_u32(Bl);

    float acc[2][4][4];
    #pragma unroll
    for (int i = 0; i < 2; i++)
        #pragma unroll
        for (int j = 0; j < 4; j++)
            #pragma unroll
            for (int e = 0; e < 4; e++) acc[i][j][e] = 0.f;

    // global loads: A 4 float4/thread, B 2 float4/thread (r=idx>>3, c=(idx&7)*4)
    float4 ra[4], rb[2];
    #pragma unroll
    for (int i = 0; i < 4; i++) {
        int idx = tid + i * 256;
        ra[i] = *(const float4*)(A + (long long)(m0 + (idx >> 3)) * K + (idx & 7) * 4);
    }
    #pragma unroll
    for (int i = 0; i < 2; i++) {
        int idx = tid + i * 256;
        rb[i] = *(const float4*)(B + (long long)(n0 + (idx >> 3)) * K + (idx & 7) * 4);
    }

    for (int k0 = 0; k0 < K; k0 += BK) {
        __syncthreads();
        #pragma unroll
        for (int i = 0; i < 4; i++) {
            int idx = tid + i * 256, r = idx >> 3, c = (idx & 7) * 4;
            cvt_hilo(ra[i], (uint2*)&Ah[r * SK + c], (uint2*)&Al[r * SK + c]);
        }
        #pragma unroll
        for (int i = 0; i < 2; i++) {
            int idx = tid + i * 256, r = idx >> 3, c = (idx & 7) * 4;
            cvt_hilo(rb[i], (uint2*)&Bh[r * SK + c], (uint2*)&Bl[r * SK + c]);
        }
        __syncthreads();

        if (k0 + BK < K) {
            #pragma unroll
            for (int i = 0; i < 4; i++) {
                int idx = tid + i * 256;
                ra[i] = *(const float4*)(A + (long long)(m0 + (idx >> 3)) * K + k0 + BK + (idx & 7) * 4);
            }
            #pragma unroll
            for (int i = 0; i < 2; i++) {
                int idx = tid + i * 256;
                rb[i] = *(const float4*)(B + (long long)(n0 + (idx >> 3)) * K + k0 + BK + (idx & 7) * 4);
            }
        }

        #pragma unroll
        for (int ks = 0; ks < 2; ks++) {
            const int arow = wm0 + (lane & 7) + ((lane >> 3) & 1) * 8;
            const int acol = ks * 16 + (lane >> 4) * 8;
            const int brow = wn0 + (lane & 7) + (lane >> 4) * 8;
            const int bcol = ((lane >> 3) & 1) * 8 + ks * 16;

            uint32_t af[2][4], afl[2][4], bf[2][4], bfl[2][4];
            #pragma unroll
            for (int f = 0; f < 2; f++) {
                uint32_t off = ((arow + f * 16) * SK + acol) * 2;
                ldsm4(af[f],  ah_b + off);
                ldsm4(afl[f], al_b + off);
            }
            #pragma unroll
            for (int p = 0; p < 2; p++) {
                uint32_t off = ((brow + p * 16) * SK + bcol) * 2;
                ldsm4(bf[p],  bh_b + off);
                ldsm4(bfl[p], bl_b + off);
            }

            #pragma unroll
            for (int mf = 0; mf < 2; mf++)
                #pragma unroll
                for (int nf = 0; nf < 4; nf++) {
                    const uint32_t* bp = &bf[nf >> 1][(nf & 1) * 2];
                    const uint32_t* lp = &bfl[nf >> 1][(nf & 1) * 2];
                    mma16(acc[mf][nf], afl[mf], bp);
                    mma16(acc[mf][nf], af[mf],  lp);
                    mma16(acc[mf][nf], af[mf],  bp);
                }
        }
    }

    // ------------------------------- epilogue ------------------------------
    #pragma unroll
    for (int mf = 0; mf < 2; mf++) {
        #pragma unroll
        for (int nf = 0; nf < 4; nf++) {
            const int gn = n0 + wn0 + nf * 8 + 2 * t;
            float b0 = 0.f, b1 = 0.f;
            if (bias) { b0 = __ldg(&bias[gn]); b1 = __ldg(&bias[gn + 1]); }
            #pragma unroll
            for (int h = 0; h < 2; h++) {   // h=0: elems 0,1 row gm; h=1: elems 2,3 row gm+8
                const int gm = m0 + wm0 + mf * 16 + g + h * 8;
                float v0 = acc[mf][nf][h * 2 + 0] * scale + b0;
                float v1 = acc[mf][nf][h * 2 + 1] * scale + b1;
                if (MODE == 0) {
                    float2 p = {v0, v1};
                    *(float2*)&C[(long long)bz * sC + (long long)gm * N + gn] = p;
                } else if (MODE == 1) {
                    int b = gm >> 11, s = gm & (SS - 1);
                    int hh = gn >> 6, d = gn & 63;
                    long long idx = (((long long)(b * HH + hh)) * SS + s) * DK + d;
                    __nv_bfloat162 hp = __floats2bfloat162_rn(v0, v1);
                    __nv_bfloat162 lp = __floats2bfloat162_rn(v0 - __bfloat162float(hp.x),
                                                              v1 - __bfloat162float(hp.y));
                    *(uint32_t*)&Ch[idx] = *(uint32_t*)&hp;
                    *(uint32_t*)&Cl[idx] = *(uint32_t*)&lp;
                } else if (MODE == 2) {
                    int b = gm >> 11, s = gm & (SS - 1);
                    int hh = gn >> 6, d = gn & 63;
                    C[(((long long)(b * HH + hh)) * DK + d) * SS + s] = v0;
                    C[(((long long)(b * HH + hh)) * DK + d + 1) * SS + s] = v1;
                } else { // MODE 3
                    int b = bz >> 4, hh = bz & 15;
                    float2 p = {v0, v1};
                    *(float2*)&C[((long long)(b * SS + gm)) * DM + hh * DK + gn] = p;
                }
            }
        }
    }
}

// ===========================================================================
// Logits GEMM: bf16 hi/lo inputs via cp.async. C = (q @ k^T)/8, per head.
// Tile 128x128, K=64 (single stage). 8 warps (4x2), warp tile 32x64.
// ===========================================================================
__global__ void __launch_bounds__(256, 2) gemm_lg(
    const __nv_bfloat16* __restrict__ Qh, const __nv_bfloat16* __restrict__ Ql,
    const __nv_bfloat16* __restrict__ Kh, const __nv_bfloat16* __restrict__ Kl,
    float* __restrict__ C)
{
    constexpr int SK = 72;   // 144B rows (9r mod 8 -> conflict-free ldsm)
    extern __shared__ __nv_bfloat16 sm[];
    __nv_bfloat16* tiles[4] = { sm, sm + 128 * SK, sm + 2 * 128 * SK, sm + 3 * 128 * SK };

    const int bh = blockIdx.z;
    const int tid = threadIdx.x, w = tid >> 5, lane = tid & 31;
    const int g = lane >> 2, t = lane & 3;
    const int m0 = blockIdx.y * 128, n0 = blockIdx.x * 128;
    const int wm0 = (w & 3) * 32, wn0 = (w >> 2) * 64;

    const __nv_bfloat16* srcs[4] = {
        Qh + (long long)bh * SS * DK + (long long)m0 * DK,
        Ql + (long long)bh * SS * DK + (long long)m0 * DK,
        Kh + (long long)bh * SS * DK + (long long)n0 * DK,
        Kl + (long long)bh * SS * DK + (long long)n0 * DK };

    #pragma unroll
    for (int a = 0; a < 4; a++) {
        uint32_t dst = smem_u32(tiles[a]);
        #pragma unroll
        for (int i = 0; i < 4; i++) {
            int idx = tid + i * 256;
            int r = idx >> 3, c = idx & 7;     // c: 16B chunk (8 halves)
            cp16(dst + (r * SK + c * 8) * 2, srcs[a] + r * 64 + c * 8);
        }
    }
    asm volatile("cp.async.commit_group;");
    asm volatile("cp.async.wait_group 0;");
    __syncthreads();

    const uint32_t ah_b = smem_u32(tiles[0]), al_b = smem_u32(tiles[1]);
    const uint32_t bh_b = smem_u32(tiles[2]), bl_b = smem_u32(tiles[3]);

    float acc[2][8][4];
    #pragma unroll
    for (int i = 0; i < 2; i++)
        #pragma unroll
        for (int j = 0; j < 8; j++)
            #pragma unroll
            for (int e = 0; e < 4; e++) acc[i][j][e] = 0.f;

    #pragma unroll
    for (int ks = 0; ks < 4; ks++) {
        const int arow = wm0 + (lane & 7) + ((lane >> 3) & 1) * 8;
        const int acol = ks * 16 + (lane >> 4) * 8;
        const int brow = wn0 + (lane & 7) + (lane >> 4) * 8;
        const int bcol = ((lane >> 3) & 1) * 8 + ks * 16;

        uint32_t af[2][4], afl[2][4], bf[4][4], bfl[4][4];
        #pragma unroll
        for (int f = 0; f < 2; f++) {
            uint32_t off = ((arow + f * 16) * SK + acol) * 2;
            ldsm4(af[f],  ah_b + off);
            ldsm4(afl[f], al_b + off);
        }
        #pragma unroll
        for (int p = 0; p < 4; p++) {
            uint32_t off = ((brow + p * 16) * SK + bcol) * 2;
            ldsm4(bf[p],  bh_b + off);
            ldsm4(bfl[p], bl_b + off);
        }

        #pragma unroll
        for (int mf = 0; mf < 2; mf++)
            #pragma unroll
            for (int nf = 0; nf < 8; nf++) {
                const uint32_t* bp = &bf[nf >> 1][(nf & 1) * 2];
                const uint32_t* lp = &bfl[nf >> 1][(nf & 1) * 2];
                mma16(acc[mf][nf], afl[mf], bp);
                mma16(acc[mf][nf], af[mf],  lp);
                mma16(acc[mf][nf], af[mf],  bp);
            }
    }

    float* Cb = C + (long long)bh * SS * SS;
    #pragma unroll
    for (int mf = 0; mf < 2; mf++)
        #pragma unroll
        for (int nf = 0; nf < 8; nf++) {
            const int gn = n0 + wn0 + nf * 8 + 2 * t;
            #pragma unroll
            for (int h = 0; h < 2; h++) {
                const int gm = m0 + wm0 + mf * 16 + g + h * 8;
                float2 p = {acc[mf][nf][h * 2] * 0.125f, acc[mf][nf][h * 2 + 1] * 0.125f};
                *(float2*)&Cb[(long long)gm * SS + gn] = p;
            }
        }
}

// ===========================================================================
// Sparsemax: one WARP per row of 2048. 64 elems/lane, shfl-only reductions.
// ===========================================================================
__global__ void __launch_bounds__(256) sparsemax_kernel(float* __restrict__ attn)
{
    const int row = blockIdx.x * 8 + (threadIdx.x >> 5);
    const int lane = threadIdx.x & 31;
    float* z = attn + (long long)row * SS;

    float4 v[16];
    #pragma unroll
    for (int i = 0; i < 16; i++) v[i] = *(const float4*)(z + i * 128 + lane * 4);

    float mx = -1e30f;
    #pragma unroll
    for (int i = 0; i < 16; i++)
        mx = fmaxf(mx, fmaxf(fmaxf(v[i].x, v[i].y), fmaxf(v[i].z, v[i].w)));
    #pragma unroll
    for (int o = 16; o; o >>= 1) mx = fmaxf(mx, __shfl_xor_sync(0xffffffffu, mx, o));

    // bisection: tau* in [mx-1, mx], invariant f(lo) >= 1
    float lo = mx - 1.f, hi = mx;
    for (int it = 0; it < 12; it++) {
        float mid = 0.5f * (lo + hi);
        float s = 0.f;
        #pragma unroll
        for (int i = 0; i < 16; i++) {
            s += fmaxf(v[i].x - mid, 0.f) + fmaxf(v[i].y - mid, 0.f);
            s += fmaxf(v[i].z - mid, 0.f) + fmaxf(v[i].w - mid, 0.f);
        }
        #pragma unroll
        for (int o = 16; o; o >>= 1) s += __shfl_xor_sync(0xffffffffu, s, o);
        if (s >= 1.f) lo = mid; else hi = mid;
    }

    // Michelot refinement from lower bound -> exact tau once support stabilizes
    float tau = lo;
    for (int it = 0; it < 8; it++) {
        float s = 0.f, c = 0.f;
        #pragma unroll
        for (int i = 0; i < 16; i++) {
            if (v[i].x > tau) { s += v[i].x; c += 1.f; }
            if (v[i].y > tau) { s += v[i].y; c += 1.f; }
            if (v[i].z > tau) { s += v[i].z; c += 1.f; }
            if (v[i].w > tau) { s += v[i].w; c += 1.f; }
        }
        #pragma unroll
        for (int o = 16; o; o >>= 1) {
            s += __shfl_xor_sync(0xffffffffu, s, o);
            c += __shfl_xor_sync(0xffffffffu, c, o);
        }
        float nt = (s - 1.f) / c;     // c >= 1 (row max always in support)
        if (nt == tau) break;
        tau = nt;
    }

    #pragma unroll
    for (int i = 0; i < 16; i++) {
        float4 o;
        o.x = fmaxf(v[i].x - tau, 0.f);
        o.y = fmaxf(v[i].y - tau, 0.f);
        o.z = fmaxf(v[i].z - tau, 0.f);
        o.w = fmaxf(v[i].w - tau, 0.f);
        *(float4*)(z + i * 128 + lane * 4) = o;
    }
}

// ---------------------------------------------------------------------------
extern "C" void kernel_launch(void* const* d_in, const int* in_sizes, int n_in,
                              void* d_out, int out_size)
{
    const float* query = (const float*)d_in[0];
    const float* key   = (const float*)d_in[1];
    const float* value = (const float*)d_in[2];
    const float* Wq  = (const float*)d_in[3];  const float* bq  = (const float*)d_in[4];
    const float* Wk  = (const float*)d_in[5];  const float* bk  = (const float*)d_in[6];
    const float* Wv  = (const float*)d_in[7];  const float* bv  = (const float*)d_in[8];
    const float* Wfc = (const float*)d_in[9];  const float* bfc = (const float*)d_in[10];

    float* out  = (float*)d_out;
    float* attn = out + OUT_ELEMS;

    __nv_bfloat16 *pqh, *pql, *pkh, *pkl;
    float *pv, *pao;
    cudaGetSymbolAddress((void**)&pqh, g_qh);
    cudaGetSymbolAddress((void**)&pql, g_ql);
    cudaGetSymbolAddress((void**)&pkh, g_kh);
    cudaGetSymbolAddress((void**)&pkl, g_kl);
    cudaGetSymbolAddress((void**)&pv,  g_v);
    cudaGetSymbolAddress((void**)&pao, g_ao);

    const int LG_SMEM = 4 * 128 * 72 * 2;  // 73728 B
    cudaFuncSetAttribute(gemm_lg, cudaFuncAttributeMaxDynamicSharedMemorySize, LG_SMEM);

    dim3 blk(256);

    // 1) Projections: q,k -> bf16 hi/lo head-major; v -> fp32 [bh][d][s]
    gemm_f32<1><<<dim3(DM/64, MM/128, 1), blk>>>(query, Wq, bq, nullptr, pqh, pql, DM, DM, 0, 0, 0, 1.f);
    gemm_f32<1><<<dim3(DM/64, MM/128, 1), blk>>>(key,   Wk, bk, nullptr, pkh, pkl, DM, DM, 0, 0, 0, 1.f);
    gemm_f32<2><<<dim3(DM/64, MM/128, 1), blk>>>(value, Wv, bv, pv, nullptr, nullptr, DM, DM, 0, 0, 0, 1.f);

    // 2) logits = q @ k^T / 8 -> attention slice of d_out
    gemm_lg<<<dim3(SS/128, SS/128, BB*HH), blk, LG_SMEM>>>(pqh, pql, pkh, pkl, attn);

    // 3) sparsemax in place (warp per row)
    sparsemax_kernel<<<BB*HH*SS/8, 256>>>(attn);

    // 4) attn_out = P @ V^T (V stored [bh][d][s]) -> (b,s,h,d) flat
    gemm_f32<3><<<dim3(1, SS/128, BB*HH), blk>>>(attn, pv, nullptr, pao, nullptr, nullptr,
                                                 DK, SS, (long long)SS*SS, (long long)DK*SS, 0, 1.f);

    // 5) output = attn_out @ Wfc^T + bfc
    gemm_f32<0><<<dim3(DM/64, MM/128, 1), blk>>>(pao, Wfc, bfc, out, nullptr, nullptr, DM, DM, 0, 0, 0, 1.f);
}